// round 1
// baseline (speedup 1.0000x reference)
#include <cuda_runtime.h>
#include <cstdint>

// ---------------------------------------------------------------------------
// NNUE fused eval, fp32 via packed f32x2 FFMA (Blackwell fma.rn.f32x2).
// One block = 128 samples, 256 threads, ~124KB dynamic shared.
// ---------------------------------------------------------------------------

#define ULL unsigned long long

__device__ __forceinline__ ULL pk2(float lo, float hi) {
    ULL r; asm("mov.b64 %0, {%1,%2};" : "=l"(r) : "f"(lo), "f"(hi)); return r;
}
__device__ __forceinline__ void upk2(ULL v, float& lo, float& hi) {
    asm("mov.b64 {%0,%1}, %2;" : "=f"(lo), "=f"(hi) : "l"(v));
}
__device__ __forceinline__ ULL fma2(ULL a, ULL b, ULL c) {
    ULL d; asm("fma.rn.f32x2 %0, %1, %2, %3;" : "=l"(d) : "l"(a), "l"(b), "l"(c)); return d;
}
__device__ __forceinline__ ULL mul2(ULL a, ULL b) {
    ULL d; asm("mul.rn.f32x2 %0, %1, %2;" : "=l"(d) : "l"(a), "l"(b)); return d;
}
__device__ __forceinline__ ULL add2(ULL a, ULL b) {
    ULL d; asm("add.rn.f32x2 %0, %1, %2;" : "=l"(d) : "l"(a), "l"(b)); return d;
}
__device__ __forceinline__ ULL relu2(ULL v) {
    float lo, hi; upk2(v, lo, hi);
    lo = fmaxf(lo, 0.0f); hi = fmaxf(hi, 0.0f);
    return pk2(lo, hi);
}
__device__ __forceinline__ ULL splat2(float v) { return pk2(v, v); }

// ---------------------------------------------------------------------------
// Precomputed weight scratch (device globals -> no allocation)
// ---------------------------------------------------------------------------
__device__ float g_Wc [98 * 64];   // combined feature-transform weights, [k][j]
__device__ float g_W0t[64 * 32];   // W0 transposed: [k][j]
__device__ float g_W1t[32 * 32];   // W1 transposed: [k][j]

__global__ void nnue_setup_kernel(const float* __restrict__ Ww,
                                  const float* __restrict__ Wb,
                                  const float* __restrict__ W0,
                                  const float* __restrict__ W1) {
    int t = blockIdx.x * blockDim.x + threadIdx.x;
    // Wc[k][j]:
    //  j <  32 (w_ path):  coeff of X[k]  (X = [white, black])  = Ww[j][k]
    //  j >= 32 (b_ path):  coeff of X[k]  where b_ input is [black, white]
    //                      -> Wb[j-32][(k + 49) % 98]
    if (t < 98 * 64) {
        int k = t >> 6, j = t & 63;
        float v;
        if (j < 32) {
            v = Ww[j * 98 + k];
        } else {
            int kk = k + 49; if (kk >= 98) kk -= 98;
            v = Wb[(j - 32) * 98 + kk];
        }
        g_Wc[t] = v;
    }
    if (t < 64 * 32) {  // W0 is [32][64] -> W0t[k][j]
        int k = t >> 5, j = t & 31;
        g_W0t[t] = W0[j * 64 + k];
    }
    if (t < 32 * 32) {  // W1 is [32][32] -> W1t[k][j]
        int k = t >> 5, j = t & 31;
        g_W1t[t] = W1[j * 32 + k];
    }
}

// ---------------------------------------------------------------------------
// Shared memory layout (float offsets). Region A (Xs) is reused for `base`,
// region B (S1) is reused for x0sh + partial sums; all reuse is across
// __syncthreads() boundaries.
// ---------------------------------------------------------------------------
constexpr int XSTR      = 132;                 // padded sample stride (16B aligned, odd/32-coprime-ish)
constexpr int OFF_XS    = 0;                   // [98][132]   input tile, transposed (k-major)
constexpr int OFF_BASE  = 0;                   // [64][132]   mixed+relu'd base (aliases XS)
constexpr int OFF_S1    = 98 * XSTR;           // [64][132]   raw stage1 outputs  (12936)
constexpr int OFF_X0    = OFF_S1;              // [32][132]   x0 (aliases S1)
constexpr int OFF_PART  = OFF_S1 + 32 * XSTR;  // [16][132]   per-group output partials
constexpr int OFF_WC    = OFF_S1 + 64 * XSTR;  // [98][64]    (21384)
constexpr int OFF_W0T   = OFF_WC + 98 * 64;    // [64][32]
constexpr int OFF_W1T   = OFF_W0T + 64 * 32;   // [32][32]
constexpr int OFF_W2    = OFF_W1T + 32 * 32;   // [64]
constexpr int OFF_B1S   = OFF_W2 + 64;         // [64] stage1 bias = [bw | bb]
constexpr int OFF_B0    = OFF_B1S + 64;        // [32]
constexpr int OFF_B1V   = OFF_B0 + 32;         // [32]
constexpr int OFF_B2    = OFF_B1V + 32;        // [1]
constexpr int OFF_POV   = ((OFF_B2 + 1 + 3) / 4) * 4;  // [128]
constexpr int SMEM_FLOATS = OFF_POV + 128;
constexpr int SMEM_BYTES  = SMEM_FLOATS * 4;   // ~124.2 KB

__global__ __launch_bounds__(256)
void nnue_kernel(const float* __restrict__ pov,
                 const float* __restrict__ white,
                 const float* __restrict__ black,
                 const float* __restrict__ bw,
                 const float* __restrict__ bb,
                 const float* __restrict__ b0,
                 const float* __restrict__ b1,
                 const float* __restrict__ W2,
                 const float* __restrict__ b2,
                 float* __restrict__ out) {
    extern __shared__ float sh[];
    const int t  = threadIdx.x;
    const int s0 = blockIdx.x * 128;

    // ---- load phase: inputs (coalesced, contiguous rows) + weights --------
    for (int i = t; i < 128 * 49; i += 256) {
        int s = i / 49;
        int k = i - s * 49;
        float wv = white[s0 * 49 + i];
        float bv = black[s0 * 49 + i];
        sh[OFF_XS + k * XSTR + s]        = wv;   // X[k]    = white[k]
        sh[OFF_XS + (49 + k) * XSTR + s] = bv;   // X[49+k] = black[k]
    }
    for (int i = t; i < 98 * 64; i += 256) sh[OFF_WC  + i] = g_Wc[i];
    for (int i = t; i < 64 * 32; i += 256) sh[OFF_W0T + i] = g_W0t[i];
    for (int i = t; i < 32 * 32; i += 256) sh[OFF_W1T + i] = g_W1t[i];
    if (t < 64)  sh[OFF_W2  + t] = W2[t];
    if (t < 64)  sh[OFF_B1S + t] = (t < 32) ? bw[t] : bb[t - 32];
    if (t < 32)  sh[OFF_B0  + t] = b0[t];
    if (t < 32)  sh[OFF_B1V + t] = b1[t];
    if (t == 0)  sh[OFF_B2]      = b2[0];
    if (t < 128) sh[OFF_POV + t] = pov[s0 + t];
    __syncthreads();

    // ---- stage 1: C[128 samples][64 outs] = X[128][98] @ Wc[98][64] -------
    // thread tile: 8 samples (4 f32x2 pairs) x 4 outputs
    const int tx = t & 15;        // sample group: samples tx*8 .. tx*8+7
    const int ty = t >> 4;        // output group: outputs ty*4 .. ty*4+3

    ULL acc[4][4];
#pragma unroll
    for (int jo = 0; jo < 4; jo++)
#pragma unroll
        for (int sp = 0; sp < 4; sp++) acc[jo][sp] = 0ull;  // packed (0,0)

    const float* xbase = &sh[OFF_XS + tx * 8];
    const float* wbase = &sh[OFF_WC + ty * 4];

#pragma unroll 2
    for (int k = 0; k < 98; k++) {
        ulonglong2 xv0 = *(const ulonglong2*)(xbase + k * XSTR);      // samples 0..3
        ulonglong2 xv1 = *(const ulonglong2*)(xbase + k * XSTR + 4);  // samples 4..7
        float4     w4  = *(const float4*)   (wbase + k * 64);
        ULL   xs[4] = {xv0.x, xv0.y, xv1.x, xv1.y};
        float wf[4] = {w4.x, w4.y, w4.z, w4.w};
#pragma unroll
        for (int jo = 0; jo < 4; jo++) {
            ULL ws = splat2(wf[jo]);
#pragma unroll
            for (int sp = 0; sp < 4; sp++)
                acc[jo][sp] = fma2(ws, xs[sp], acc[jo][sp]);
        }
    }

    // bias + store raw S1 (transposed: [j][sample])
#pragma unroll
    for (int jo = 0; jo < 4; jo++) {
        ULL bsp = splat2(sh[OFF_B1S + ty * 4 + jo]);
#pragma unroll
        for (int sp = 0; sp < 4; sp++) {
            ULL v = add2(acc[jo][sp], bsp);
            *(ULL*)&sh[OFF_S1 + (ty * 4 + jo) * XSTR + tx * 8 + sp * 2] = v;
        }
    }
    __syncthreads();

    // ---- perspective mix + relu: base[j] = relu(p*S1[j] + (1-p)*S1[j^32]) -
#pragma unroll
    for (int sp = 0; sp < 4; sp++) {
        float p0 = sh[OFF_POV + tx * 8 + sp * 2];
        float p1 = sh[OFF_POV + tx * 8 + sp * 2 + 1];
        ULL pp = pk2(p0, p1);
        ULL op = pk2(1.0f - p0, 1.0f - p1);
#pragma unroll
        for (int jo = 0; jo < 4; jo++) {
            int j = ty * 4 + jo;
            ULL a  = *(const ULL*)&sh[OFF_S1 + j        * XSTR + tx * 8 + sp * 2];
            ULL bq = *(const ULL*)&sh[OFF_S1 + (j ^ 32) * XSTR + tx * 8 + sp * 2];
            ULL v  = fma2(pp, a, mul2(op, bq));
            *(ULL*)&sh[OFF_BASE + j * XSTR + tx * 8 + sp * 2] = relu2(v);
        }
    }
    __syncthreads();

    // ---- stage 2a: x0[32] = relu(base @ W0t + b0); also partial dot with W2
    // thread tile: 4 samples (2 pairs) x 4 outputs
    const int tx2 = t & 31;   // samples tx2*4 .. tx2*4+3
    const int ty2 = t >> 5;   // outputs ty2*4 .. ty2*4+3  (ty2 in 0..7)

    ULL a0[4][2];
#pragma unroll
    for (int jo = 0; jo < 4; jo++) { a0[jo][0] = 0ull; a0[jo][1] = 0ull; }

    {
        const float* xb = &sh[OFF_BASE + tx2 * 4];
        const float* wb_ = &sh[OFF_W0T + ty2 * 4];
#pragma unroll 4
        for (int k = 0; k < 64; k++) {
            ulonglong2 xv = *(const ulonglong2*)(xb + k * XSTR);
            float4     w4 = *(const float4*)(wb_ + k * 32);
            ULL   xs[2] = {xv.x, xv.y};
            float wf[4] = {w4.x, w4.y, w4.z, w4.w};
#pragma unroll
            for (int jo = 0; jo < 4; jo++) {
                ULL ws = splat2(wf[jo]);
#pragma unroll
                for (int sp = 0; sp < 2; sp++)
                    a0[jo][sp] = fma2(ws, xs[sp], a0[jo][sp]);
            }
        }
    }

    ULL pac[2] = {0ull, 0ull};
#pragma unroll
    for (int jo = 0; jo < 4; jo++) {
        int j = ty2 * 4 + jo;
        ULL bsp = splat2(sh[OFF_B0 + j]);
        ULL w2s = splat2(sh[OFF_W2 + j]);
#pragma unroll
        for (int sp = 0; sp < 2; sp++) {
            ULL v = relu2(add2(a0[jo][sp], bsp));
            *(ULL*)&sh[OFF_X0 + j * XSTR + tx2 * 4 + sp * 2] = v;
            pac[sp] = fma2(w2s, v, pac[sp]);
        }
    }
#pragma unroll
    for (int sp = 0; sp < 2; sp++)
        *(ULL*)&sh[OFF_PART + ty2 * XSTR + tx2 * 4 + sp * 2] = pac[sp];
    __syncthreads();

    // ---- stage 2b: x1 = relu(x0 @ W1t + b1); partial dot with W2[32:] -----
    ULL a1[4][2];
#pragma unroll
    for (int jo = 0; jo < 4; jo++) { a1[jo][0] = 0ull; a1[jo][1] = 0ull; }

    {
        const float* xb = &sh[OFF_X0 + tx2 * 4];
        const float* wb_ = &sh[OFF_W1T + ty2 * 4];
#pragma unroll 4
        for (int k = 0; k < 32; k++) {
            ulonglong2 xv = *(const ulonglong2*)(xb + k * XSTR);
            float4     w4 = *(const float4*)(wb_ + k * 32);
            ULL   xs[2] = {xv.x, xv.y};
            float wf[4] = {w4.x, w4.y, w4.z, w4.w};
#pragma unroll
            for (int jo = 0; jo < 4; jo++) {
                ULL ws = splat2(wf[jo]);
#pragma unroll
                for (int sp = 0; sp < 2; sp++)
                    a1[jo][sp] = fma2(ws, xs[sp], a1[jo][sp]);
            }
        }
    }

    ULL pac1[2] = {0ull, 0ull};
#pragma unroll
    for (int jo = 0; jo < 4; jo++) {
        int j = ty2 * 4 + jo;
        ULL bsp = splat2(sh[OFF_B1V + j]);
        ULL w2s = splat2(sh[OFF_W2 + 32 + j]);
#pragma unroll
        for (int sp = 0; sp < 2; sp++) {
            ULL v = relu2(add2(a1[jo][sp], bsp));
            pac1[sp] = fma2(w2s, v, pac1[sp]);
        }
    }
#pragma unroll
    for (int sp = 0; sp < 2; sp++)
        *(ULL*)&sh[OFF_PART + (8 + ty2) * XSTR + tx2 * 4 + sp * 2] = pac1[sp];
    __syncthreads();

    // ---- final: out[s] = sum of 16 partials + b2 ---------------------------
    if (t < 128) {
        float sum = sh[OFF_B2];
#pragma unroll
        for (int g = 0; g < 16; g++)
            sum += sh[OFF_PART + g * XSTR + t];
        out[s0 + t] = sum;
    }
}

// ---------------------------------------------------------------------------
extern "C" void kernel_launch(void* const* d_in, const int* in_sizes, int n_in,
                              void* d_out, int out_size) {
    const float* pov   = (const float*)d_in[0];
    const float* white = (const float*)d_in[1];
    const float* black = (const float*)d_in[2];
    const float* Ww    = (const float*)d_in[3];
    const float* bw    = (const float*)d_in[4];
    const float* Wb    = (const float*)d_in[5];
    const float* bb    = (const float*)d_in[6];
    const float* W0    = (const float*)d_in[7];
    const float* b0    = (const float*)d_in[8];
    const float* W1    = (const float*)d_in[9];
    const float* b1    = (const float*)d_in[10];
    const float* W2    = (const float*)d_in[11];
    const float* b2    = (const float*)d_in[12];

    const int B = in_sizes[0];  // pov is [B,1] -> B elements

    cudaFuncSetAttribute(nnue_kernel,
                         cudaFuncAttributeMaxDynamicSharedMemorySize, SMEM_BYTES);

    nnue_setup_kernel<<<25, 256>>>(Ww, Wb, W0, W1);
    nnue_kernel<<<B / 128, 256, SMEM_BYTES>>>(pov, white, black, bw, bb,
                                              b0, b1, W2, b2, (float*)d_out);
}

// round 2
// speedup vs baseline: 1.9429x; 1.9429x over previous
#include <cuda_runtime.h>
#include <cstdint>

#define ULL unsigned long long

__device__ __forceinline__ ULL pk2(float lo, float hi) {
    ULL r; asm("mov.b64 %0, {%1,%2};" : "=l"(r) : "f"(lo), "f"(hi)); return r;
}
__device__ __forceinline__ void upk2(ULL v, float& lo, float& hi) {
    asm("mov.b64 {%0,%1}, %2;" : "=f"(lo), "=f"(hi) : "l"(v));
}
__device__ __forceinline__ ULL fma2(ULL a, ULL b, ULL c) {
    ULL d; asm("fma.rn.f32x2 %0, %1, %2, %3;" : "=l"(d) : "l"(a), "l"(b), "l"(c)); return d;
}
__device__ __forceinline__ ULL mul2(ULL a, ULL b) {
    ULL d; asm("mul.rn.f32x2 %0, %1, %2;" : "=l"(d) : "l"(a), "l"(b)); return d;
}
__device__ __forceinline__ ULL add2(ULL a, ULL b) {
    ULL d; asm("add.rn.f32x2 %0, %1, %2;" : "=l"(d) : "l"(a), "l"(b)); return d;
}
__device__ __forceinline__ ULL relu2(ULL v) {
    float lo, hi; upk2(v, lo, hi);
    lo = fmaxf(lo, 0.0f); hi = fmaxf(hi, 0.0f);
    return pk2(lo, hi);
}
__device__ __forceinline__ ULL splat2(float v) { return pk2(v, v); }

// ---------------------------------------------------------------------------
// Precomputed weights (device globals, no allocation)
// g_WcP: paired layout [98][64]: entry k*64 + ty*4 + c  holds weight for
//        output j = (c<2 ? 2ty+c : 32 + 2ty + (c-2)), input k of combined X.
// ---------------------------------------------------------------------------
__device__ float g_WcP[98 * 64];
__device__ float g_W0t[64 * 32];   // [k][j]
__device__ float g_W1t[32 * 32];   // [k][j]

__global__ void nnue_setup_kernel(const float* __restrict__ Ww,
                                  const float* __restrict__ Wb,
                                  const float* __restrict__ W0,
                                  const float* __restrict__ W1) {
    int t = blockIdx.x * blockDim.x + threadIdx.x;
    if (t < 98 * 64) {
        int k = t >> 6, q = t & 63;
        int ty = q >> 2, c = q & 3;
        int j = (c < 2) ? (2 * ty + c) : (32 + 2 * ty + (c - 2));
        float v;
        if (j < 32) {
            v = Ww[j * 98 + k];
        } else {
            int kk = k + 49; if (kk >= 98) kk -= 98;
            v = Wb[(j - 32) * 98 + kk];
        }
        g_WcP[t] = v;
    }
    if (t < 64 * 32) { int k = t >> 5, j = t & 31; g_W0t[t] = W0[j * 64 + k]; }
    if (t < 32 * 32) { int k = t >> 5, j = t & 31; g_W1t[t] = W1[j * 32 + k]; }
}

// ---------------------------------------------------------------------------
// Shared layout (float offsets). XSTR = 130 (stride ≡ 2 mod 32 -> 2-way max).
// Region A (XS) reused as `base`; region B (WcP copy) reused as x0 + partials.
// ---------------------------------------------------------------------------
constexpr int XSTR     = 130;
constexpr int OFF_XS   = 0;                   // [98][130]
constexpr int OFF_BASE = 0;                   // [64][130]  (aliases XS)
constexpr int OFF_WC   = 98 * XSTR;           // [98][64]   = 12740
constexpr int OFF_X0   = OFF_WC;              // [32][130]  (aliases WC)
constexpr int OFF_PART = OFF_WC + 32 * XSTR;  // [16][130]
constexpr int OFF_W0T  = OFF_WC + 98 * 64;    // 19012
constexpr int OFF_W1T  = OFF_W0T + 64 * 32;   // 21060
constexpr int OFF_B1P  = OFF_W1T + 32 * 32;   // 22084 [16]x float4
constexpr int OFF_W2   = OFF_B1P + 64;        // 22148 [64]
constexpr int OFF_B0   = OFF_W2 + 64;         // [32]
constexpr int OFF_B1V  = OFF_B0 + 32;         // [32]
constexpr int OFF_B2   = OFF_B1V + 32;        // [1]
constexpr int OFF_POV  = OFF_B2 + 2;          // [128], even offset (8B aligned)
constexpr int SMEM_FLOATS = OFF_POV + 128;
constexpr int SMEM_BYTES  = SMEM_FLOATS * 4;  // ~89.6 KB -> 2 blocks/SM

__global__ __launch_bounds__(256, 2)
void nnue_kernel(const float* __restrict__ pov,
                 const float* __restrict__ white,
                 const float* __restrict__ black,
                 const float* __restrict__ bwp,
                 const float* __restrict__ bbp,
                 const float* __restrict__ b0p,
                 const float* __restrict__ b1p,
                 const float* __restrict__ W2p,
                 const float* __restrict__ b2p,
                 float* __restrict__ out) {
    extern __shared__ float sh[];
    const int t  = threadIdx.x;
    const int s0 = blockIdx.x * 128;

    // ---- load phase -------------------------------------------------------
    // inputs: float4 coalesced reads, transpose-scatter stores (2-way max)
    {
        const float4* w4p = (const float4*)(white + s0 * 49);
        const float4* b4p = (const float4*)(black + s0 * 49);
        for (int i4 = t; i4 < 1568; i4 += 256) {
            float4 wv = w4p[i4];
            float4 bv = b4p[i4];
            float wf[4] = {wv.x, wv.y, wv.z, wv.w};
            float bf[4] = {bv.x, bv.y, bv.z, bv.w};
            int ibase = i4 * 4;
#pragma unroll
            for (int c = 0; c < 4; c++) {
                int i = ibase + c;
                int s = (unsigned)i / 49u;
                int k = i - s * 49;
                sh[OFF_XS + k * XSTR + s]        = wf[c];
                sh[OFF_XS + (49 + k) * XSTR + s] = bf[c];
            }
        }
    }
    for (int i = t; i < 98 * 64; i += 256) sh[OFF_WC  + i] = g_WcP[i];
    for (int i = t; i < 64 * 32; i += 256) sh[OFF_W0T + i] = g_W0t[i];
    for (int i = t; i < 32 * 32; i += 256) sh[OFF_W1T + i] = g_W1t[i];
    if (t < 16) {
        // paired stage-1 bias: {bw[2t], bw[2t+1], bb[2t], bb[2t+1]}
        sh[OFF_B1P + t * 4 + 0] = bwp[2 * t];
        sh[OFF_B1P + t * 4 + 1] = bwp[2 * t + 1];
        sh[OFF_B1P + t * 4 + 2] = bbp[2 * t];
        sh[OFF_B1P + t * 4 + 3] = bbp[2 * t + 1];
    }
    if (t < 64)  sh[OFF_W2  + t] = W2p[t];
    if (t < 32)  sh[OFF_B0  + t] = b0p[t];
    if (t < 32)  sh[OFF_B1V + t] = b1p[t];
    if (t == 0)  sh[OFF_B2]      = b2p[0];
    if (t < 128) sh[OFF_POV + t] = pov[s0 + t];
    __syncthreads();

    // ---- stage 1: 128 samples x 64 outputs, K=98 --------------------------
    // thread: samples s = tx*2 + g*32 (4 f32x2 pairs), outputs {2ty,2ty+1,+32,+33}
    const int tx = t & 15;
    const int ty = t >> 4;

    ULL acc[4][4];
#pragma unroll
    for (int c = 0; c < 4; c++)
#pragma unroll
        for (int g = 0; g < 4; g++) acc[c][g] = 0ull;

    {
        const float* xb = sh + OFF_XS + tx * 2;
        const float* wb = sh + OFF_WC + ty * 4;

        ULL   xc[4];
        float4 wc;
#pragma unroll
        for (int g = 0; g < 4; g++) xc[g] = *(const ULL*)(xb + g * 32);
        wc = *(const float4*)(wb);

#pragma unroll 2
        for (int k = 0; k < 98; k++) {
            // prefetch k+1 (row 98 reads spill into WcP region: in-bounds, unused)
            ULL xn[4];
            const float* xr = xb + (k + 1) * XSTR;
#pragma unroll
            for (int g = 0; g < 4; g++) xn[g] = *(const ULL*)(xr + g * 32);
            float4 wn = *(const float4*)(wb + (k + 1) * 64);

            float wf[4] = {wc.x, wc.y, wc.z, wc.w};
#pragma unroll
            for (int c = 0; c < 4; c++) {
                ULL ws = splat2(wf[c]);
#pragma unroll
                for (int g = 0; g < 4; g++)
                    acc[c][g] = fma2(ws, xc[g], acc[c][g]);
            }
#pragma unroll
            for (int g = 0; g < 4; g++) xc[g] = xn[g];
            wc = wn;
        }
    }

    // ---- bias + perspective mix + relu, all in registers ------------------
    {
        float4 bp = *(const float4*)(sh + OFF_B1P + ty * 4);
        float bL[2] = {bp.x, bp.y};
        float bH[2] = {bp.z, bp.w};
#pragma unroll
        for (int g = 0; g < 4; g++) {
            ULL pp = *(const ULL*)(sh + OFF_POV + tx * 2 + g * 32);
            float p0, p1; upk2(pp, p0, p1);
            ULL op = pk2(1.0f - p0, 1.0f - p1);
#pragma unroll
            for (int d = 0; d < 2; d++) {
                ULL sL = add2(acc[d][g],     splat2(bL[d]));
                ULL sH = add2(acc[d + 2][g], splat2(bH[d]));
                ULL v0 = fma2(pp, sL, mul2(op, sH));   // base[j]
                ULL v1 = fma2(pp, sH, mul2(op, sL));   // base[j+32]
                acc[d][g]     = relu2(v0);
                acc[d + 2][g] = relu2(v1);
            }
        }
    }
    __syncthreads();   // all reads of XS done before overwriting with base

    {
#pragma unroll
        for (int g = 0; g < 4; g++) {
            int s = tx * 2 + g * 32;
#pragma unroll
            for (int d = 0; d < 2; d++) {
                *(ULL*)(sh + OFF_BASE + (2 * ty + d)      * XSTR + s) = acc[d][g];
                *(ULL*)(sh + OFF_BASE + (2 * ty + d + 32) * XSTR + s) = acc[d + 2][g];
            }
        }
    }
    __syncthreads();

    // ---- stage 2a: x0 = relu(base @ W0t + b0), + partial W2 dot -----------
    // thread: samples s = tx2*2 + sp*64 (2 pairs), outputs ty2*4..+3
    const int tx2 = t & 31;
    const int ty2 = t >> 5;

    ULL a0[4][2];
#pragma unroll
    for (int c = 0; c < 4; c++) { a0[c][0] = 0ull; a0[c][1] = 0ull; }
    {
        const float* xb = sh + OFF_BASE + tx2 * 2;
        const float* wb = sh + OFF_W0T + ty2 * 4;
#pragma unroll 4
        for (int k = 0; k < 64; k++) {
            ULL x0v = *(const ULL*)(xb + k * XSTR);
            ULL x1v = *(const ULL*)(xb + k * XSTR + 64);
            float4 w4 = *(const float4*)(wb + k * 32);
            float wf[4] = {w4.x, w4.y, w4.z, w4.w};
#pragma unroll
            for (int c = 0; c < 4; c++) {
                ULL ws = splat2(wf[c]);
                a0[c][0] = fma2(ws, x0v, a0[c][0]);
                a0[c][1] = fma2(ws, x1v, a0[c][1]);
            }
        }
    }
    {
        ULL pac[2] = {0ull, 0ull};
#pragma unroll
        for (int c = 0; c < 4; c++) {
            int j = ty2 * 4 + c;
            ULL bs  = splat2(sh[OFF_B0 + j]);
            ULL w2s = splat2(sh[OFF_W2 + j]);
#pragma unroll
            for (int sp = 0; sp < 2; sp++) {
                ULL v = relu2(add2(a0[c][sp], bs));
                *(ULL*)(sh + OFF_X0 + j * XSTR + tx2 * 2 + sp * 64) = v;
                pac[sp] = fma2(w2s, v, pac[sp]);
            }
        }
#pragma unroll
        for (int sp = 0; sp < 2; sp++)
            *(ULL*)(sh + OFF_PART + ty2 * XSTR + tx2 * 2 + sp * 64) = pac[sp];
    }
    __syncthreads();

    // ---- stage 2b: x1 = relu(x0 @ W1t + b1), + partial W2[32:] dot --------
    ULL a1[4][2];
#pragma unroll
    for (int c = 0; c < 4; c++) { a1[c][0] = 0ull; a1[c][1] = 0ull; }
    {
        const float* xb = sh + OFF_X0 + tx2 * 2;
        const float* wb = sh + OFF_W1T + ty2 * 4;
#pragma unroll 4
        for (int k = 0; k < 32; k++) {
            ULL x0v = *(const ULL*)(xb + k * XSTR);
            ULL x1v = *(const ULL*)(xb + k * XSTR + 64);
            float4 w4 = *(const float4*)(wb + k * 32);
            float wf[4] = {w4.x, w4.y, w4.z, w4.w};
#pragma unroll
            for (int c = 0; c < 4; c++) {
                ULL ws = splat2(wf[c]);
                a1[c][0] = fma2(ws, x0v, a1[c][0]);
                a1[c][1] = fma2(ws, x1v, a1[c][1]);
            }
        }
    }
    {
        ULL pac[2] = {0ull, 0ull};
#pragma unroll
        for (int c = 0; c < 4; c++) {
            int j = ty2 * 4 + c;
            ULL bs  = splat2(sh[OFF_B1V + j]);
            ULL w2s = splat2(sh[OFF_W2 + 32 + j]);
#pragma unroll
            for (int sp = 0; sp < 2; sp++) {
                ULL v = relu2(add2(a1[c][sp], bs));
                pac[sp] = fma2(w2s, v, pac[sp]);
            }
        }
#pragma unroll
        for (int sp = 0; sp < 2; sp++)
            *(ULL*)(sh + OFF_PART + (8 + ty2) * XSTR + tx2 * 2 + sp * 64) = pac[sp];
    }
    __syncthreads();

    // ---- final: out[s] = sum of 16 partials + b2 --------------------------
    if (t < 128) {
        float sum = sh[OFF_B2];
#pragma unroll
        for (int g = 0; g < 16; g++)
            sum += sh[OFF_PART + g * XSTR + t];
        out[s0 + t] = sum;
    }
}

// ---------------------------------------------------------------------------
extern "C" void kernel_launch(void* const* d_in, const int* in_sizes, int n_in,
                              void* d_out, int out_size) {
    const float* pov   = (const float*)d_in[0];
    const float* white = (const float*)d_in[1];
    const float* black = (const float*)d_in[2];
    const float* Ww    = (const float*)d_in[3];
    const float* bw    = (const float*)d_in[4];
    const float* Wb    = (const float*)d_in[5];
    const float* bb    = (const float*)d_in[6];
    const float* W0    = (const float*)d_in[7];
    const float* b0    = (const float*)d_in[8];
    const float* W1    = (const float*)d_in[9];
    const float* b1    = (const float*)d_in[10];
    const float* W2    = (const float*)d_in[11];
    const float* b2    = (const float*)d_in[12];

    const int B = in_sizes[0];

    cudaFuncSetAttribute(nnue_kernel,
                         cudaFuncAttributeMaxDynamicSharedMemorySize, SMEM_BYTES);

    nnue_setup_kernel<<<25, 256>>>(Ww, Wb, W0, W1);
    nnue_kernel<<<B / 128, 256, SMEM_BYTES>>>(pov, white, black, bw, bb,
                                              b0, b1, W2, b2, (float*)d_out);
}